// round 16
// baseline (speedup 1.0000x reference)
#include <cuda_runtime.h>
#include <cuda_bf16.h>
#include <cstdint>
#include <cstdio>

#define B_ 64
#define S_ 64
#define P_ 32
#define D_ 512
#define E_ 512
#define H_ 512
#define H3_ 1536
#define A_ 256
#define NH_ 4
#define OUT_ 16
#define BS_ (B_*S_)

// d_out layout: out[64,16] | states[B,S,2H] | context[B,4096] | alpha_actv[B,NH,S]
#define STATES_OFF 1024
#define CONTEXT_OFF (1024 + BS_*2*H_)
#define ALPHA_OFF (CONTEXT_OFF + B_*NH_*2*H_)

#define WPAD 516   // GRU weight row stride (bf16 elems)
#define GST 24     // bgemm smem row stride (bf16 elems)

typedef unsigned long long ull;
typedef unsigned short us;

// ---------------- scratch (device globals; no allocation allowed) -------------
__device__ float g_xg[2][BS_*H3_];
__device__ float g_m1[BS_*A_];
__device__ us g_vec_h[BS_*D_],  g_vec_l[BS_*D_];
__device__ us g_emb_h[BS_*E_],  g_emb_l[BS_*E_];
__device__ us g_st_h[BS_*2*H_], g_st_l[BS_*2*H_];
__device__ us g_wemb_h[E_*D_],  g_wemb_l[E_*D_];
__device__ us g_wihf_h[H3_*E_], g_wihf_l[H3_*E_];
__device__ us g_wihb_h[H3_*E_], g_wihb_l[H3_*E_];
__device__ us g_w1_h[A_*2*H_],  g_w1_l[A_*2*H_];
__device__ unsigned g_cnt8[8][32];
__device__ unsigned g_gen8[8][32];

union U64F2 { ull u; float2 f; };

// ---------------- fence-free group grid barrier (16 blocks, acq/rel) ----------
__device__ __forceinline__ void gbar_grp(int grp){
    __syncthreads();
    if (threadIdx.x == 0){
        unsigned* cnt = &g_cnt8[grp][0];
        unsigned* gen = &g_gen8[grp][0];
        unsigned g;
        asm volatile("ld.relaxed.gpu.u32 %0, [%1];" : "=r"(g) : "l"(gen) : "memory");
        unsigned old;
        asm volatile("atom.release.gpu.add.u32 %0, [%1], 1;"
                     : "=r"(old) : "l"(cnt) : "memory");
        if (old == 15u){
            asm volatile("st.relaxed.gpu.u32 [%0], 0;" :: "l"(cnt) : "memory");
            asm volatile("st.release.gpu.u32 [%0], %1;" :: "l"(gen), "r"(g + 1u) : "memory");
        } else {
            unsigned cur;
            do {
                asm volatile("ld.acquire.gpu.u32 %0, [%1];" : "=r"(cur) : "l"(gen) : "memory");
            } while (cur == g);
        }
    }
    __syncthreads();
}

// ---------------- split-bf16 helpers -------------------------------------------
__device__ __forceinline__ void bsplit4(float4 v, ull& hi, ull& lo){
    __nv_bfloat16 h0 = __float2bfloat16_rn(v.x);
    __nv_bfloat16 h1 = __float2bfloat16_rn(v.y);
    __nv_bfloat16 h2 = __float2bfloat16_rn(v.z);
    __nv_bfloat16 h3 = __float2bfloat16_rn(v.w);
    __nv_bfloat16 l0 = __float2bfloat16_rn(v.x - __bfloat162float(h0));
    __nv_bfloat16 l1 = __float2bfloat16_rn(v.y - __bfloat162float(h1));
    __nv_bfloat16 l2 = __float2bfloat16_rn(v.z - __bfloat162float(h2));
    __nv_bfloat16 l3 = __float2bfloat16_rn(v.w - __bfloat162float(h3));
    hi = (ull)__bfloat16_as_ushort(h0) | ((ull)__bfloat16_as_ushort(h1) << 16)
       | ((ull)__bfloat16_as_ushort(h2) << 32) | ((ull)__bfloat16_as_ushort(h3) << 48);
    lo = (ull)__bfloat16_as_ushort(l0) | ((ull)__bfloat16_as_ushort(l1) << 16)
       | ((ull)__bfloat16_as_ushort(l2) << 32) | ((ull)__bfloat16_as_ushort(l3) << 48);
}
__device__ __forceinline__ void bsplit1(float x, us& h, us& l){
    __nv_bfloat16 hh = __float2bfloat16_rn(x);
    h = __bfloat16_as_ushort(hh);
    l = __bfloat16_as_ushort(__float2bfloat16_rn(x - __bfloat162float(hh)));
}
__device__ __forceinline__ void mma16816(float* c, const unsigned* a, const unsigned* b){
    asm volatile(
        "mma.sync.aligned.m16n8k16.row.col.f32.bf16.bf16.f32 "
        "{%0,%1,%2,%3}, {%4,%5,%6,%7}, {%8,%9}, {%0,%1,%2,%3};"
        : "+f"(c[0]), "+f"(c[1]), "+f"(c[2]), "+f"(c[3])
        : "r"(a[0]), "r"(a[1]), "r"(a[2]), "r"(a[3]), "r"(b[0]), "r"(b[1]));
}
__device__ __forceinline__ void ldsm4(unsigned* r, const void* p){
    unsigned a = (unsigned)__cvta_generic_to_shared(p);
    asm volatile("ldmatrix.sync.aligned.m8n8.x4.shared.b16 {%0,%1,%2,%3}, [%4];"
                 : "=r"(r[0]), "=r"(r[1]), "=r"(r[2]), "=r"(r[3]) : "r"(a));
}

// ---------------- weight splitter ----------------------------------------------
__global__ __launch_bounds__(256) void k_splitw(const float* __restrict__ src,
                                                us* __restrict__ h, us* __restrict__ l,
                                                int n4){
    int i = blockIdx.x*256 + threadIdx.x;
    if (i < n4){
        float4 v = ((const float4*)src)[i];
        ull hi, lo;
        bsplit4(v, hi, lo);
        ((ull*)h)[i] = hi;
        ((ull*)l)[i] = lo;
    }
}

// ---------------- fused conv + weighted-sum (writes split vec) -----------------
__global__ __launch_bounds__(256) void k_conv_vec(const float* __restrict__ inp,
                                                  const float* __restrict__ conv_w,
                                                  const float* __restrict__ conv_b){
    extern __shared__ float tile[];          // P_*D_ = 16384 floats = 64KB
    __shared__ float cw[D_];
    __shared__ float convp[P_];
    int bs = blockIdx.x;
    int tid = threadIdx.x;
    const float4* src4 = (const float4*)(inp + (size_t)bs*P_*D_);
    float4* t4 = (float4*)tile;
    for (int i = tid; i < D_; i += 256) cw[i] = conv_w[i];
    for (int i = tid; i < P_*D_/4; i += 256) t4[i] = src4[i];
    __syncthreads();
    int wid = tid >> 5, lane = tid & 31;
    float cb = conv_b[0];
    for (int p = wid; p < P_; p += 8){
        float s = 0.f;
        for (int d = lane; d < D_; d += 32) s += tile[p*D_+d]*cw[d];
        #pragma unroll
        for (int o = 16; o > 0; o >>= 1) s += __shfl_xor_sync(0xffffffffu, s, o);
        if (lane == 0) convp[p] = s + cb;
    }
    __syncthreads();
    for (int d = tid; d < D_; d += 256){
        float acc = 0.f;
        #pragma unroll
        for (int p = 0; p < P_; p++) acc += convp[p]*tile[p*D_+d];
        us h, l;
        bsplit1(acc, h, l);
        g_vec_h[(size_t)bs*D_ + d] = h;
        g_vec_l[(size_t)bs*D_ + d] = l;
    }
}

// ---------------- split-bf16 HMMA GEMM v3 (pre-split operands) ------------------
// A/B given as bf16 hi/lo arrays. outSplit: write Ch/Cl; else Cf (fp32).
__global__ __launch_bounds__(256) void k_bgemm(const us* __restrict__ Ah,
                                               const us* __restrict__ Al,
                                               const us* __restrict__ Bh,
                                               const us* __restrict__ Bl,
                                               const us* __restrict__ Bh2,
                                               const us* __restrict__ Bl2,
                                               float* __restrict__ Cf,
                                               us* __restrict__ Ch,
                                               us* __restrict__ Cl,
                                               int M, int N, int K,
                                               const float* __restrict__ bias,
                                               const float* __restrict__ bias2,
                                               int doClip, int permA, int outSplit){
    __shared__ __align__(16) us sAh[2][128*GST];
    __shared__ __align__(16) us sAl[2][128*GST];
    __shared__ __align__(16) us sBh[2][64*GST];
    __shared__ __align__(16) us sBl[2][64*GST];

    int tid = threadIdx.x;
    int wid = tid >> 5, lane = tid & 31;
    if (blockIdx.z){ Bh = Bh2; Bl = Bl2; bias = bias2; Cf += (size_t)M*N; }
    int mbase = blockIdx.y * 128;
    int nbase = blockIdx.x * 64;

    int ia0 = tid*2, ia1 = tid*2 + 1;
    int ra0 = ia0 >> 2, ca0 = (ia0 & 3)*4;
    int ra1 = ia1 >> 2, ca1 = (ia1 & 3)*4;
    int rb  = tid >> 2, cb = (tid & 3)*4;
    int ga0 = mbase + ra0, ga1 = mbase + ra1;
    if (permA){ ga0 = (ga0 & 63)*64 + (ga0 >> 6); ga1 = (ga1 & 63)*64 + (ga1 >> 6); }
    const us* AhR0 = Ah + (size_t)ga0*K + ca0;
    const us* AlR0 = Al + (size_t)ga0*K + ca0;
    const us* AhR1 = Ah + (size_t)ga1*K + ca1;
    const us* AlR1 = Al + (size_t)ga1*K + ca1;
    const us* BhR  = Bh + (size_t)(nbase + rb)*K + cb;
    const us* BlR  = Bl + (size_t)(nbase + rb)*K + cb;

    int m0 = (wid & 3) * 32;
    int n0 = (wid >> 2) * 32;
    int g = lane >> 2, tg = lane & 3;

    int rin = lane & 7, sel = lane >> 3;
    int offA0 = (m0 + (sel & 1)*8 + rin)*GST + (sel >> 1)*8;
    int offA1 = offA0 + 16*GST;
    int offB0 = (n0 + (sel >> 1)*8 + rin)*GST + (sel & 1)*8;
    int offB1 = offB0 + 16*GST;

    float acc[2][4][4];
    #pragma unroll
    for (int i = 0; i < 2; i++)
        #pragma unroll
        for (int jn = 0; jn < 4; jn++)
            #pragma unroll
            for (int e = 0; e < 4; e++) acc[i][jn][e] = 0.f;

    int nk = K >> 4;
    ull a0h = *(const ull*)AhR0, a0l = *(const ull*)AlR0;
    ull a1h = *(const ull*)AhR1, a1l = *(const ull*)AlR1;
    ull bvh = *(const ull*)BhR,  bvl = *(const ull*)BlR;
    *(ull*)&sAh[0][ra0*GST + ca0] = a0h;  *(ull*)&sAl[0][ra0*GST + ca0] = a0l;
    *(ull*)&sAh[0][ra1*GST + ca1] = a1h;  *(ull*)&sAl[0][ra1*GST + ca1] = a1l;
    *(ull*)&sBh[0][rb*GST + cb]   = bvh;  *(ull*)&sBl[0][rb*GST + cb]   = bvl;
    __syncthreads();

    for (int kt = 0; kt < nk; kt++){
        int cur = kt & 1;
        if (kt + 1 < nk){
            a0h = *(const ull*)(AhR0 + (kt+1)*16);  a0l = *(const ull*)(AlR0 + (kt+1)*16);
            a1h = *(const ull*)(AhR1 + (kt+1)*16);  a1l = *(const ull*)(AlR1 + (kt+1)*16);
            bvh = *(const ull*)(BhR  + (kt+1)*16);  bvl = *(const ull*)(BlR  + (kt+1)*16);
        }

        unsigned ah[2][4], al[2][4], bh[2][4], bl[2][4];
        ldsm4(ah[0], &sAh[cur][offA0]);
        ldsm4(ah[1], &sAh[cur][offA1]);
        ldsm4(al[0], &sAl[cur][offA0]);
        ldsm4(al[1], &sAl[cur][offA1]);
        ldsm4(bh[0], &sBh[cur][offB0]);
        ldsm4(bh[1], &sBh[cur][offB1]);
        ldsm4(bl[0], &sBl[cur][offB0]);
        ldsm4(bl[1], &sBl[cur][offB1]);

        #pragma unroll
        for (int i = 0; i < 2; i++){
            #pragma unroll
            for (int jn = 0; jn < 4; jn++){
                const unsigned* pbh = &bh[jn >> 1][(jn & 1)*2];
                const unsigned* pbl = &bl[jn >> 1][(jn & 1)*2];
                mma16816(acc[i][jn], ah[i], pbh);
                mma16816(acc[i][jn], ah[i], pbl);
                mma16816(acc[i][jn], al[i], pbh);
            }
        }

        if (kt + 1 < nk){
            int nxt = cur ^ 1;
            *(ull*)&sAh[nxt][ra0*GST + ca0] = a0h;  *(ull*)&sAl[nxt][ra0*GST + ca0] = a0l;
            *(ull*)&sAh[nxt][ra1*GST + ca1] = a1h;  *(ull*)&sAl[nxt][ra1*GST + ca1] = a1l;
            *(ull*)&sBh[nxt][rb*GST + cb]   = bvh;  *(ull*)&sBl[nxt][rb*GST + cb]   = bvl;
        }
        __syncthreads();
    }

    #pragma unroll
    for (int i = 0; i < 2; i++){
        int row0 = mbase + m0 + i*16 + g;
        int row1 = row0 + 8;
        #pragma unroll
        for (int jn = 0; jn < 4; jn++){
            int col = nbase + n0 + jn*8 + tg*2;
            float2 v0 = make_float2(acc[i][jn][0], acc[i][jn][1]);
            float2 v1 = make_float2(acc[i][jn][2], acc[i][jn][3]);
            if (bias){
                float2 bb = *(const float2*)&bias[col];
                v0.x += bb.x; v0.y += bb.y;
                v1.x += bb.x; v1.y += bb.y;
            }
            if (doClip){
                v0.x = fminf(fmaxf(v0.x,-1.f),1.f); v0.y = fminf(fmaxf(v0.y,-1.f),1.f);
                v1.x = fminf(fmaxf(v1.x,-1.f),1.f); v1.y = fminf(fmaxf(v1.y,-1.f),1.f);
            }
            if (outSplit){
                us h0a,l0a,h0b,l0b,h1a,l1a,h1b,l1b;
                bsplit1(v0.x, h0a, l0a);  bsplit1(v0.y, h0b, l0b);
                bsplit1(v1.x, h1a, l1a);  bsplit1(v1.y, h1b, l1b);
                *(unsigned*)&Ch[(size_t)row0*N + col] = (unsigned)h0a | ((unsigned)h0b << 16);
                *(unsigned*)&Cl[(size_t)row0*N + col] = (unsigned)l0a | ((unsigned)l0b << 16);
                *(unsigned*)&Ch[(size_t)row1*N + col] = (unsigned)h1a | ((unsigned)h1b << 16);
                *(unsigned*)&Cl[(size_t)row1*N + col] = (unsigned)l1a | ((unsigned)l1b << 16);
            } else {
                *(float2*)&Cf[(size_t)row0*N + col] = v0;
                *(float2*)&Cf[(size_t)row1*N + col] = v1;
            }
        }
    }
}

// ---------------- persistent bidirectional GRU v12 ----------------------------
// R14 structure (single accumulators) + pre-split h staging (pure copies),
// writes states fp32 AND states hi/lo for the m1 GEMM + its own next step.
__global__ __launch_bounds__(256) void k_gru(const float* __restrict__ w_hh_f,
                                             const float* __restrict__ w_hh_b,
                                             const float* __restrict__ b_hh_f,
                                             const float* __restrict__ b_hh_b,
                                             float* __restrict__ states){
    extern __shared__ us smu[];
    us* wHi = smu;                       // 96*WPAD
    us* wLo = smu + 96*WPAD;             // 96*WPAD
    us* hHi = smu + 192*WPAD;            // 16*WPAD
    us* hLo = hHi + 16*WPAD;             // 16*WPAD
    float* epi = (float*)hHi;            // 96*16 floats, reused post-mma

    int blk = blockIdx.x;        // 128
    int dir = blk >> 6;
    int rr = blk & 63;
    int jc = rr >> 2, bq = rr & 3;
    int jbase = jc * 32;
    int bbase = bq * 16;
    int grp = dir*4 + bq;        // 0..7
    const float* whh = dir ? w_hh_b : w_hh_f;
    const float* bhh = dir ? b_hh_b : b_hh_f;
    const float* xg = g_xg[dir];
    int tid = threadIdx.x;
    int wid = tid >> 5, lane = tid & 31;
    int g = lane >> 2, tg = lane & 3;
    int jp = tid >> 3;           // 0..31
    int bp = tid & 7;            // 0..7
    int j  = jbase + jp;
    int b0 = bbase + bp*2;

    // ---- one-time: load + split weights (rows: gate*32 + jl) ----
    {
        const float4* w4 = (const float4*)whh;
        for (int idx = tid; idx < 96*128; idx += 256){
            int row = idx >> 7;          // gate*32 + jl
            int kq = idx & 127;
            int gg = row >> 5, jl = row & 31;
            float4 v = w4[(size_t)(gg*H_ + jbase + jl)*128 + kq];
            ull hi, lo;
            bsplit4(v, hi, lo);
            *(ull*)&wHi[row*WPAD + kq*4] = hi;
            *(ull*)&wLo[row*WPAD + kq*4] = lo;
        }
    }

    float bhr = bhh[j], bhz = bhh[H_+j], bhn = bhh[2*H_+j];

    // preload xg for t=0
    int tidx0 = dir ? (S_-1) : 0;
    const float* xA0 = xg + ((size_t)(tidx0*B_ + b0))*H3_;
    const float* xB0 = xA0 + H3_;
    float xr0 = xA0[j], xz0 = xA0[H_+j], xn0 = xA0[2*H_+j];
    float xr1 = xB0[j], xz1 = xB0[H_+j], xn1 = xB0[2*H_+j];

    int m0r = wid * 16;          // mma warp's row base (wid < 6)

    for (int t = 0; t < S_; t++){
        int tidx = dir ? (S_-1-t) : t;
        int ptidx = dir ? (S_-t) : (t-1);   // previous output time (valid t>=1)

        // stage h hi/lo from pre-split states (pure ull copies); t=0 -> zeros
        float hp0, hp1;
        if (t == 0){
            #pragma unroll
            for (int i = 0; i < 8; i++){
                int gi = tid + (i << 8);
                int bb = gi >> 7, kq = gi & 127;
                *(ull*)&hHi[bb*WPAD + kq*4] = 0ULL;
                *(ull*)&hLo[bb*WPAD + kq*4] = 0ULL;
            }
            hp0 = 0.f; hp1 = 0.f;
        } else {
            #pragma unroll
            for (int i = 0; i < 8; i++){
                int gi = tid + (i << 8);
                int bb = gi >> 7, kq = gi & 127;
                size_t base = ((size_t)((bbase+bb)*S_ + ptidx))*(2*H_) + dir*H_ + kq*4;
                *(ull*)&hHi[bb*WPAD + kq*4] = *(const ull*)&g_st_h[base];
                *(ull*)&hLo[bb*WPAD + kq*4] = *(const ull*)&g_st_l[base];
            }
            hp0 = states[((size_t)b0*S_ + ptidx)*(2*H_) + dir*H_ + j];
            hp1 = states[((size_t)(b0+1)*S_ + ptidx)*(2*H_) + dir*H_ + j];
        }
        // next xg issued early (hidden under mma)
        float nxr0=0,nxz0=0,nxn0=0,nxr1=0,nxz1=0,nxn1=0;
        if (t + 1 < S_){
            int ntidx = dir ? (S_-2-t) : (t+1);
            const float* nA = xg + ((size_t)(ntidx*B_ + b0))*H3_;
            const float* nB = nA + H3_;
            nxr0 = nA[j]; nxz0 = nA[H_+j]; nxn0 = nA[2*H_+j];
            nxr1 = nB[j]; nxz1 = nB[H_+j]; nxn1 = nB[2*H_+j];
        }
        __syncthreads();

        float acc0[4] = {0.f,0.f,0.f,0.f};
        float acc1[4] = {0.f,0.f,0.f,0.f};
        if (wid < 6){
            int rA0 = (m0r + g)*WPAD;
            int rA8 = (m0r + g + 8)*WPAD;
            int rB0 = g*WPAD;
            int rB8 = (8 + g)*WPAD;
            #pragma unroll 4
            for (int kc = 0; kc < 32; kc++){
                int kb = kc*16 + tg*2;
                unsigned ah[4], al[4], b0h[2], b0l[2], b1h[2], b1l[2];
                ah[0] = *(const unsigned*)&wHi[rA0 + kb];
                ah[1] = *(const unsigned*)&wHi[rA8 + kb];
                ah[2] = *(const unsigned*)&wHi[rA0 + kb + 8];
                ah[3] = *(const unsigned*)&wHi[rA8 + kb + 8];
                al[0] = *(const unsigned*)&wLo[rA0 + kb];
                al[1] = *(const unsigned*)&wLo[rA8 + kb];
                al[2] = *(const unsigned*)&wLo[rA0 + kb + 8];
                al[3] = *(const unsigned*)&wLo[rA8 + kb + 8];
                b0h[0] = *(const unsigned*)&hHi[rB0 + kb];
                b0h[1] = *(const unsigned*)&hHi[rB0 + kb + 8];
                b0l[0] = *(const unsigned*)&hLo[rB0 + kb];
                b0l[1] = *(const unsigned*)&hLo[rB0 + kb + 8];
                b1h[0] = *(const unsigned*)&hHi[rB8 + kb];
                b1h[1] = *(const unsigned*)&hHi[rB8 + kb + 8];
                b1l[0] = *(const unsigned*)&hLo[rB8 + kb];
                b1l[1] = *(const unsigned*)&hLo[rB8 + kb + 8];
                mma16816(acc0, ah, b0h);
                mma16816(acc0, ah, b0l);
                mma16816(acc0, al, b0h);
                mma16816(acc1, ah, b1h);
                mma16816(acc1, ah, b1l);
                mma16816(acc1, al, b1h);
            }
        }
        __syncthreads();   // all hHi/hLo reads done -> safe to reuse as epi

        if (wid < 6){
            int r0 = (m0r + g)*16;
            int r8 = (m0r + g + 8)*16;
            epi[r0 + tg*2]          = acc0[0];
            epi[r0 + tg*2 + 1]      = acc0[1];
            epi[r8 + tg*2]          = acc0[2];
            epi[r8 + tg*2 + 1]      = acc0[3];
            epi[r0 + 8 + tg*2]      = acc1[0];
            epi[r0 + 8 + tg*2 + 1]  = acc1[1];
            epi[r8 + 8 + tg*2]      = acc1[2];
            epi[r8 + 8 + tg*2 + 1]  = acc1[3];
        }
        __syncthreads();

        float sr0 = epi[jp*16 + bp*2],        sr1 = epi[jp*16 + bp*2 + 1];
        float sz0 = epi[(32+jp)*16 + bp*2],   sz1 = epi[(32+jp)*16 + bp*2 + 1];
        float sn0 = epi[(64+jp)*16 + bp*2],   sn1 = epi[(64+jp)*16 + bp*2 + 1];

        float r0 = 1.f/(1.f+expf(-(xr0 + sr0 + bhr)));
        float r1 = 1.f/(1.f+expf(-(xr1 + sr1 + bhr)));
        float z0 = 1.f/(1.f+expf(-(xz0 + sz0 + bhz)));
        float z1 = 1.f/(1.f+expf(-(xz1 + sz1 + bhz)));
        float n0 = tanhf(xn0 + r0*(sn0 + bhn));
        float n1 = tanhf(xn1 + r1*(sn1 + bhn));
        float h0 = (1.f-z0)*n0 + z0*hp0;
        float h1 = (1.f-z1)*n1 + z1*hp1;

        size_t o0 = ((size_t)b0*S_ + tidx)*(2*H_) + dir*H_ + j;
        size_t o1 = ((size_t)(b0+1)*S_ + tidx)*(2*H_) + dir*H_ + j;
        states[o0] = h0;
        states[o1] = h1;
        us hh, hl;
        bsplit1(h0, hh, hl);  g_st_h[o0] = hh;  g_st_l[o0] = hl;
        bsplit1(h1, hh, hl);  g_st_h[o1] = hh;  g_st_l[o1] = hl;

        if (t + 1 < S_) gbar_grp(grp);

        xr0=nxr0; xz0=nxz0; xn0=nxn0; xr1=nxr1; xz1=nxz1; xn1=nxn1;
    }
}

// ---------------- alpha = m1 @ att_w2^T, softmax over S -----------------------
__global__ __launch_bounds__(256) void k_alpha(const float* __restrict__ att_w2,
                                               float* __restrict__ alpha_out){
    __shared__ float w2s[NH_*A_];
    __shared__ float al[NH_*S_];
    int b = blockIdx.x, tid = threadIdx.x;
    for (int i = tid; i < NH_*A_; i += 256) w2s[i] = att_w2[i];
    __syncthreads();
    int s = tid >> 2, h = tid & 3;
    const float* m1r = g_m1 + ((size_t)(b*S_ + s))*A_;
    float acc = 0.f;
    #pragma unroll 4
    for (int k = 0; k < A_; k++) acc += m1r[k]*w2s[h*A_+k];
    al[h*S_+s] = acc;
    __syncthreads();
    int wid = tid >> 5, lane = tid & 31;
    if (wid < NH_){
        float v0 = al[wid*S_+lane], v1 = al[wid*S_+lane+32];
        float mx = fmaxf(v0, v1);
        #pragma unroll
        for (int o = 16; o > 0; o >>= 1) mx = fmaxf(mx, __shfl_xor_sync(0xffffffffu, mx, o));
        float e0 = expf(v0-mx), e1 = expf(v1-mx);
        float sm = e0 + e1;
        #pragma unroll
        for (int o = 16; o > 0; o >>= 1) sm += __shfl_xor_sync(0xffffffffu, sm, o);
        float inv = 1.f/sm;
        alpha_out[(b*NH_+wid)*S_ + lane]      = e0*inv;
        alpha_out[(b*NH_+wid)*S_ + lane + 32] = e1*inv;
    }
}

// ---------------- context = alpha @ states ------------------------------------
__global__ __launch_bounds__(512) void k_context(const float* __restrict__ states,
                                                 const float* __restrict__ alpha_in,
                                                 float* __restrict__ context){
    __shared__ float als[NH_*S_];
    int b = blockIdx.x, tid = threadIdx.x;
    if (tid < NH_*S_) als[tid] = alpha_in[b*NH_*S_ + tid];
    __syncthreads();
    float a0[NH_], a1[NH_];
    #pragma unroll
    for (int h = 0; h < NH_; h++){ a0[h] = 0.f; a1[h] = 0.f; }
    const float* st = states + (size_t)b*S_*2*H_;
    for (int s = 0; s < S_; s++){
        float v0 = st[s*2*H_ + tid];
        float v1 = st[s*2*H_ + H_ + tid];
        #pragma unroll
        for (int h = 0; h < NH_; h++){
            float a = als[h*S_+s];
            a0[h] += a*v0; a1[h] += a*v1;
        }
    }
    float* cb = context + (size_t)b*NH_*2*H_;
    #pragma unroll
    for (int h = 0; h < NH_; h++){
        cb[h*2*H_ + tid]      = a0[h];
        cb[h*2*H_ + H_ + tid] = a1[h];
    }
}

// ---------------- final linear + softmax --------------------------------------
__global__ __launch_bounds__(512) void k_final(const float* __restrict__ context,
                                               const float* __restrict__ lin_w,
                                               const float* __restrict__ lin_b,
                                               float* __restrict__ out){
    __shared__ float red[OUT_];
    int b = blockIdx.x, tid = threadIdx.x, w = tid >> 5, lane = tid & 31;
    const float* cx = context + (size_t)b*4096;
    const float* lw = lin_w + (size_t)w*4096;
    float acc = 0.f;
    for (int k = lane; k < 4096; k += 32) acc += cx[k]*lw[k];
    #pragma unroll
    for (int o = 16; o > 0; o >>= 1) acc += __shfl_xor_sync(0xffffffffu, acc, o);
    if (lane == 0) red[w] = acc + lin_b[w];
    __syncthreads();
    if (tid < 32){
        float v = (lane < OUT_) ? red[lane] : -1e30f;
        float mx = v;
        #pragma unroll
        for (int o = 16; o > 0; o >>= 1) mx = fmaxf(mx, __shfl_xor_sync(0xffffffffu, mx, o));
        float e = (lane < OUT_) ? expf(v - mx) : 0.f;
        float sm = e;
        #pragma unroll
        for (int o = 16; o > 0; o >>= 1) sm += __shfl_xor_sync(0xffffffffu, sm, o);
        if (lane < OUT_) out[b*OUT_ + lane] = e/sm;
    }
}

// ---------------- launch ------------------------------------------------------
extern "C" void kernel_launch(void* const* d_in, const int* in_sizes, int n_in,
                              void* d_out, int out_size){
    const float* inputs  = (const float*)d_in[0];
    const float* conv_w  = (const float*)d_in[2];
    const float* conv_b  = (const float*)d_in[3];
    const float* w_embed = (const float*)d_in[4];
    const float* w_ih_f  = (const float*)d_in[5];
    const float* w_hh_f  = (const float*)d_in[6];
    const float* b_ih_f  = (const float*)d_in[7];
    const float* b_hh_f  = (const float*)d_in[8];
    const float* w_ih_b  = (const float*)d_in[9];
    const float* w_hh_b  = (const float*)d_in[10];
    const float* b_ih_b  = (const float*)d_in[11];
    const float* b_hh_b  = (const float*)d_in[12];
    const float* att_w1  = (const float*)d_in[13];
    const float* att_w2  = (const float*)d_in[14];
    const float* lin_w   = (const float*)d_in[15];
    const float* lin_b   = (const float*)d_in[16];

    float* out     = (float*)d_out;
    float* states  = out + STATES_OFF;
    float* context = out + CONTEXT_OFF;
    float* alpha   = out + ALPHA_OFF;

    void *p_xg, *p_m1;
    void *p_vh, *p_vl, *p_eh, *p_el, *p_sh, *p_sl;
    void *p_weh, *p_wel, *p_wfh, *p_wfl, *p_wbh, *p_wbl, *p_w1h, *p_w1l;
    cudaGetSymbolAddress(&p_xg,  g_xg);
    cudaGetSymbolAddress(&p_m1,  g_m1);
    cudaGetSymbolAddress(&p_vh, g_vec_h);   cudaGetSymbolAddress(&p_vl, g_vec_l);
    cudaGetSymbolAddress(&p_eh, g_emb_h);   cudaGetSymbolAddress(&p_el, g_emb_l);
    cudaGetSymbolAddress(&p_sh, g_st_h);    cudaGetSymbolAddress(&p_sl, g_st_l);
    cudaGetSymbolAddress(&p_weh, g_wemb_h); cudaGetSymbolAddress(&p_wel, g_wemb_l);
    cudaGetSymbolAddress(&p_wfh, g_wihf_h); cudaGetSymbolAddress(&p_wfl, g_wihf_l);
    cudaGetSymbolAddress(&p_wbh, g_wihb_h); cudaGetSymbolAddress(&p_wbl, g_wihb_l);
    cudaGetSymbolAddress(&p_w1h, g_w1_h);   cudaGetSymbolAddress(&p_w1l, g_w1_l);
    float* xg0 = (float*)p_xg;
    float* m1  = (float*)p_m1;
    us *vh=(us*)p_vh, *vl=(us*)p_vl, *eh=(us*)p_eh, *el=(us*)p_el;
    us *sh=(us*)p_sh, *sl=(us*)p_sl;
    us *weh=(us*)p_weh, *wel=(us*)p_wel, *wfh=(us*)p_wfh, *wfl=(us*)p_wfl;
    us *wbh=(us*)p_wbh, *wbl=(us*)p_wbl, *w1h=(us*)p_w1h, *w1l=(us*)p_w1l;

    const int conv_smem = P_*D_*4;                       // 65536
    const int gru_smem  = (192*WPAD + 32*WPAD) * 2;      // 231168
    cudaFuncSetAttribute(k_conv_vec, cudaFuncAttributeMaxDynamicSharedMemorySize, conv_smem);
    cudaFuncSetAttribute(k_gru,      cudaFuncAttributeMaxDynamicSharedMemorySize, gru_smem);

    // 0) pre-split the feed-forward weights (bf16 hi/lo)
    k_splitw<<<(E_*D_/4 + 255)/256, 256>>>(w_embed, weh, wel, E_*D_/4);
    k_splitw<<<(H3_*E_/4 + 255)/256, 256>>>(w_ih_f, wfh, wfl, H3_*E_/4);
    k_splitw<<<(H3_*E_/4 + 255)/256, 256>>>(w_ih_b, wbh, wbl, H3_*E_/4);
    k_splitw<<<(A_*2*H_/4 + 255)/256, 256>>>(att_w1, w1h, w1l, A_*2*H_/4);
    // 1) conv + weighted-sum (writes pre-split vec)
    k_conv_vec<<<BS_, 256, conv_smem>>>(inputs, conv_w, conv_b);
    // 2) emb = clip(vec @ w_embed^T)  -> split output only
    k_bgemm<<<dim3(E_/64, BS_/128, 1), 256>>>(vh, vl, weh, wel, weh, wel,
                                              nullptr, eh, el,
                                              BS_, E_, D_, nullptr, nullptr, 1, 0, 1);
    // 3) xg = emb([S,B] permuted) @ w_ih^T + b_ih, BOTH dirs -> fp32
    k_bgemm<<<dim3(H3_/64, BS_/128, 2), 256>>>(eh, el, wfh, wfl, wbh, wbl,
                                               xg0, nullptr, nullptr,
                                               BS_, H3_, E_, b_ih_f, b_ih_b, 0, 1, 0);
    // 4) persistent bidirectional GRU (pre-split h pipeline) -> states
    k_gru<<<128, 256, gru_smem>>>(w_hh_f, w_hh_b, b_hh_f, b_hh_b, states);
    // 5) m1 = clip(states @ att_w1^T) -> fp32
    k_bgemm<<<dim3(A_/64, BS_/128, 1), 256>>>(sh, sl, w1h, w1l, w1h, w1l,
                                              m1, nullptr, nullptr,
                                              BS_, A_, 2*H_, nullptr, nullptr, 1, 0, 0);
    // 6) alpha = softmax_S(m1 @ att_w2^T), transposed to [B,NH,S]
    k_alpha<<<B_, 256>>>(att_w2, alpha);
    // 7) context
    k_context<<<B_, 512>>>(states, alpha, context);
    // 8) out = softmax(context @ lin_w^T + lin_b)
    k_final<<<B_, 512>>>(context, lin_w, lin_b, out);
}

// round 17
// speedup vs baseline: 1.0831x; 1.0831x over previous
#include <cuda_runtime.h>
#include <cuda_bf16.h>
#include <cstdint>
#include <cstdio>

#define B_ 64
#define S_ 64
#define P_ 32
#define D_ 512
#define E_ 512
#define H_ 512
#define H3_ 1536
#define A_ 256
#define NH_ 4
#define OUT_ 16
#define BS_ (B_*S_)

// d_out layout: out[64,16] | states[B,S,2H] | context[B,4096] | alpha_actv[B,NH,S]
#define STATES_OFF 1024
#define CONTEXT_OFF (1024 + BS_*2*H_)
#define ALPHA_OFF (CONTEXT_OFF + B_*NH_*2*H_)

#define WPAD 516   // GRU weight row stride (bf16 elems)
#define GST 24     // bgemm smem row stride (bf16 elems)

typedef unsigned long long ull;

// ---------------- scratch (device globals; no allocation allowed) -------------
__device__ float g_vec[BS_*D_];
__device__ float g_emb[BS_*E_];
__device__ float g_xg[2][BS_*H3_];
__device__ float g_m1[BS_*A_];
__device__ unsigned g_cnt8[8][32];      // 8 barrier groups, padded
__device__ unsigned g_gen8[8][32];

union U64F2 { ull u; float2 f; };

// ---------------- fence-free group grid barrier (16 blocks, acq/rel) ----------
__device__ __forceinline__ void gbar_grp(int grp){
    __syncthreads();
    if (threadIdx.x == 0){
        unsigned* cnt = &g_cnt8[grp][0];
        unsigned* gen = &g_gen8[grp][0];
        unsigned g;
        asm volatile("ld.relaxed.gpu.u32 %0, [%1];" : "=r"(g) : "l"(gen) : "memory");
        unsigned old;
        asm volatile("atom.release.gpu.add.u32 %0, [%1], 1;"
                     : "=r"(old) : "l"(cnt) : "memory");
        if (old == 15u){
            asm volatile("st.relaxed.gpu.u32 [%0], 0;" :: "l"(cnt) : "memory");
            asm volatile("st.release.gpu.u32 [%0], %1;" :: "l"(gen), "r"(g + 1u) : "memory");
        } else {
            unsigned cur;
            do {
                asm volatile("ld.acquire.gpu.u32 %0, [%1];" : "=r"(cur) : "l"(gen) : "memory");
            } while (cur == g);
        }
    }
    __syncthreads();
}

// ---------------- split-bf16 helpers (validated in R11/R12) --------------------
__device__ __forceinline__ void bsplit4(float4 v, ull& hi, ull& lo){
    __nv_bfloat16 h0 = __float2bfloat16_rn(v.x);
    __nv_bfloat16 h1 = __float2bfloat16_rn(v.y);
    __nv_bfloat16 h2 = __float2bfloat16_rn(v.z);
    __nv_bfloat16 h3 = __float2bfloat16_rn(v.w);
    __nv_bfloat16 l0 = __float2bfloat16_rn(v.x - __bfloat162float(h0));
    __nv_bfloat16 l1 = __float2bfloat16_rn(v.y - __bfloat162float(h1));
    __nv_bfloat16 l2 = __float2bfloat16_rn(v.z - __bfloat162float(h2));
    __nv_bfloat16 l3 = __float2bfloat16_rn(v.w - __bfloat162float(h3));
    hi = (ull)__bfloat16_as_ushort(h0) | ((ull)__bfloat16_as_ushort(h1) << 16)
       | ((ull)__bfloat16_as_ushort(h2) << 32) | ((ull)__bfloat16_as_ushort(h3) << 48);
    lo = (ull)__bfloat16_as_ushort(l0) | ((ull)__bfloat16_as_ushort(l1) << 16)
       | ((ull)__bfloat16_as_ushort(l2) << 32) | ((ull)__bfloat16_as_ushort(l3) << 48);
}
__device__ __forceinline__ void mma16816(float* c, const unsigned* a, const unsigned* b){
    asm volatile(
        "mma.sync.aligned.m16n8k16.row.col.f32.bf16.bf16.f32 "
        "{%0,%1,%2,%3}, {%4,%5,%6,%7}, {%8,%9}, {%0,%1,%2,%3};"
        : "+f"(c[0]), "+f"(c[1]), "+f"(c[2]), "+f"(c[3])
        : "r"(a[0]), "r"(a[1]), "r"(a[2]), "r"(a[3]), "r"(b[0]), "r"(b[1]));
}
__device__ __forceinline__ void ldsm4(unsigned* r, const void* p){
    unsigned a = (unsigned)__cvta_generic_to_shared(p);
    asm volatile("ldmatrix.sync.aligned.m8n8.x4.shared.b16 {%0,%1,%2,%3}, [%4];"
                 : "=r"(r[0]), "=r"(r[1]), "=r"(r[2]), "=r"(r[3]) : "r"(a));
}

// ---------------- fused conv + weighted-sum (reads inputs ONCE) ---------------
__global__ __launch_bounds__(256) void k_conv_vec(const float* __restrict__ inp,
                                                  const float* __restrict__ conv_w,
                                                  const float* __restrict__ conv_b){
    extern __shared__ float tile[];          // P_*D_ = 16384 floats = 64KB
    __shared__ float cw[D_];
    __shared__ float convp[P_];
    int bs = blockIdx.x;
    int tid = threadIdx.x;
    const float4* src4 = (const float4*)(inp + (size_t)bs*P_*D_);
    float4* t4 = (float4*)tile;
    for (int i = tid; i < D_; i += 256) cw[i] = conv_w[i];
    for (int i = tid; i < P_*D_/4; i += 256) t4[i] = src4[i];
    __syncthreads();
    int wid = tid >> 5, lane = tid & 31;
    float cb = conv_b[0];
    for (int p = wid; p < P_; p += 8){
        float s = 0.f;
        for (int d = lane; d < D_; d += 32) s += tile[p*D_+d]*cw[d];
        #pragma unroll
        for (int o = 16; o > 0; o >>= 1) s += __shfl_xor_sync(0xffffffffu, s, o);
        if (lane == 0) convp[p] = s + cb;
    }
    __syncthreads();
    for (int d = tid; d < D_; d += 256){
        float acc = 0.f;
        #pragma unroll
        for (int p = 0; p < P_; p++) acc += convp[p]*tile[p*D_+d];
        g_vec[(size_t)bs*D_ + d] = acc;
    }
}

// ---------------- split-bf16 HMMA GEMM v2 (R13/R14-proven, verbatim) -----------
__global__ __launch_bounds__(256) void k_bgemm(const float* __restrict__ A,
                                               const float* __restrict__ Bw,
                                               const float* __restrict__ Bw2,
                                               float* __restrict__ C,
                                               int M, int N, int K,
                                               const float* __restrict__ bias,
                                               const float* __restrict__ bias2,
                                               int doClip, int permA){
    __shared__ __align__(16) unsigned short sAh[2][128*GST];
    __shared__ __align__(16) unsigned short sAl[2][128*GST];
    __shared__ __align__(16) unsigned short sBh[2][64*GST];
    __shared__ __align__(16) unsigned short sBl[2][64*GST];

    int tid = threadIdx.x;
    int wid = tid >> 5, lane = tid & 31;
    if (blockIdx.z){ Bw = Bw2; bias = bias2; C += (size_t)M*N; }
    int mbase = blockIdx.y * 128;
    int nbase = blockIdx.x * 64;

    int ia0 = tid*2, ia1 = tid*2 + 1;
    int ra0 = ia0 >> 2, ca0 = (ia0 & 3)*4;
    int ra1 = ia1 >> 2, ca1 = (ia1 & 3)*4;
    int rb  = tid >> 2, cb = (tid & 3)*4;
    int ga0 = mbase + ra0, ga1 = mbase + ra1;
    if (permA){ ga0 = (ga0 & 63)*64 + (ga0 >> 6); ga1 = (ga1 & 63)*64 + (ga1 >> 6); }
    const float* ApR0 = A + (size_t)ga0*K + ca0;
    const float* ApR1 = A + (size_t)ga1*K + ca1;
    const float* BpR  = Bw + (size_t)(nbase + rb)*K + cb;

    int m0 = (wid & 3) * 32;
    int n0 = (wid >> 2) * 32;
    int g = lane >> 2, tg = lane & 3;

    int rin = lane & 7, sel = lane >> 3;
    int offA0 = (m0 + (sel & 1)*8 + rin)*GST + (sel >> 1)*8;
    int offA1 = offA0 + 16*GST;
    int offB0 = (n0 + (sel >> 1)*8 + rin)*GST + (sel & 1)*8;
    int offB1 = offB0 + 16*GST;

    float acc[2][4][4];
    #pragma unroll
    for (int i = 0; i < 2; i++)
        #pragma unroll
        for (int jn = 0; jn < 4; jn++)
            #pragma unroll
            for (int e = 0; e < 4; e++) acc[i][jn][e] = 0.f;

    int nk = K >> 4;
    float4 av0 = *(const float4*)ApR0;
    float4 av1 = *(const float4*)ApR1;
    float4 bv  = *(const float4*)BpR;
    {
        ull hi, lo;
        bsplit4(av0, hi, lo);
        *(ull*)&sAh[0][ra0*GST + ca0] = hi;  *(ull*)&sAl[0][ra0*GST + ca0] = lo;
        bsplit4(av1, hi, lo);
        *(ull*)&sAh[0][ra1*GST + ca1] = hi;  *(ull*)&sAl[0][ra1*GST + ca1] = lo;
        bsplit4(bv, hi, lo);
        *(ull*)&sBh[0][rb*GST + cb] = hi;    *(ull*)&sBl[0][rb*GST + cb] = lo;
    }
    __syncthreads();

    for (int kt = 0; kt < nk; kt++){
        int cur = kt & 1;
        if (kt + 1 < nk){
            av0 = *(const float4*)(ApR0 + (kt+1)*16);
            av1 = *(const float4*)(ApR1 + (kt+1)*16);
            bv  = *(const float4*)(BpR  + (kt+1)*16);
        }

        unsigned ah[2][4], al[2][4], bh[2][4], bl[2][4];
        ldsm4(ah[0], &sAh[cur][offA0]);
        ldsm4(ah[1], &sAh[cur][offA1]);
        ldsm4(al[0], &sAl[cur][offA0]);
        ldsm4(al[1], &sAl[cur][offA1]);
        ldsm4(bh[0], &sBh[cur][offB0]);
        ldsm4(bh[1], &sBh[cur][offB1]);
        ldsm4(bl[0], &sBl[cur][offB0]);
        ldsm4(bl[1], &sBl[cur][offB1]);

        #pragma unroll
        for (int i = 0; i < 2; i++){
            #pragma unroll
            for (int jn = 0; jn < 4; jn++){
                const unsigned* pbh = &bh[jn >> 1][(jn & 1)*2];
                const unsigned* pbl = &bl[jn >> 1][(jn & 1)*2];
                mma16816(acc[i][jn], ah[i], pbh);
                mma16816(acc[i][jn], ah[i], pbl);
                mma16816(acc[i][jn], al[i], pbh);
            }
        }

        if (kt + 1 < nk){
            int nxt = cur ^ 1;
            ull hi, lo;
            bsplit4(av0, hi, lo);
            *(ull*)&sAh[nxt][ra0*GST + ca0] = hi;  *(ull*)&sAl[nxt][ra0*GST + ca0] = lo;
            bsplit4(av1, hi, lo);
            *(ull*)&sAh[nxt][ra1*GST + ca1] = hi;  *(ull*)&sAl[nxt][ra1*GST + ca1] = lo;
            bsplit4(bv, hi, lo);
            *(ull*)&sBh[nxt][rb*GST + cb] = hi;    *(ull*)&sBl[nxt][rb*GST + cb] = lo;
        }
        __syncthreads();
    }

    #pragma unroll
    for (int i = 0; i < 2; i++){
        int row0 = mbase + m0 + i*16 + g;
        int row1 = row0 + 8;
        #pragma unroll
        for (int jn = 0; jn < 4; jn++){
            int col = nbase + n0 + jn*8 + tg*2;
            float2 v0 = make_float2(acc[i][jn][0], acc[i][jn][1]);
            float2 v1 = make_float2(acc[i][jn][2], acc[i][jn][3]);
            if (bias){
                float2 bb = *(const float2*)&bias[col];
                v0.x += bb.x; v0.y += bb.y;
                v1.x += bb.x; v1.y += bb.y;
            }
            if (doClip){
                v0.x = fminf(fmaxf(v0.x,-1.f),1.f); v0.y = fminf(fmaxf(v0.y,-1.f),1.f);
                v1.x = fminf(fmaxf(v1.x,-1.f),1.f); v1.y = fminf(fmaxf(v1.y,-1.f),1.f);
            }
            *(float2*)&C[(size_t)row0*N + col] = v0;
            *(float2*)&C[(size_t)row1*N + col] = v1;
        }
    }
}

// ---------------- persistent bidirectional GRU v10 (R14-proven, verbatim) -----
__global__ __launch_bounds__(256) void k_gru(const float* __restrict__ w_hh_f,
                                             const float* __restrict__ w_hh_b,
                                             const float* __restrict__ b_hh_f,
                                             const float* __restrict__ b_hh_b,
                                             float* __restrict__ states){
    extern __shared__ unsigned short smu[];
    unsigned short* wHi = smu;                       // 96*WPAD
    unsigned short* wLo = smu + 96*WPAD;             // 96*WPAD
    unsigned short* hHi = smu + 192*WPAD;            // 16*WPAD
    unsigned short* hLo = hHi + 16*WPAD;             // 16*WPAD
    float* epi = (float*)hHi;                        // 96*16 floats, reused post-mma

    int blk = blockIdx.x;        // 128
    int dir = blk >> 6;
    int rr = blk & 63;
    int jc = rr >> 2, bq = rr & 3;
    int jbase = jc * 32;
    int bbase = bq * 16;
    int grp = dir*4 + bq;        // 0..7
    const float* whh = dir ? w_hh_b : w_hh_f;
    const float* bhh = dir ? b_hh_b : b_hh_f;
    const float* xg = g_xg[dir];
    int tid = threadIdx.x;
    int wid = tid >> 5, lane = tid & 31;
    int g = lane >> 2, tg = lane & 3;
    int jp = tid >> 3;           // 0..31
    int bp = tid & 7;            // 0..7
    int j  = jbase + jp;
    int b0 = bbase + bp*2;

    // ---- one-time: load + split weights (rows: gate*32 + jl) ----
    {
        const float4* w4 = (const float4*)whh;
        for (int idx = tid; idx < 96*128; idx += 256){
            int row = idx >> 7;          // gate*32 + jl
            int kq = idx & 127;
            int gg = row >> 5, jl = row & 31;
            float4 v = w4[(size_t)(gg*H_ + jbase + jl)*128 + kq];
            ull hi, lo;
            bsplit4(v, hi, lo);
            *(ull*)&wHi[row*WPAD + kq*4] = hi;
            *(ull*)&wLo[row*WPAD + kq*4] = lo;
        }
    }

    float bhr = bhh[j], bhz = bhh[H_+j], bhn = bhh[2*H_+j];

    // preload xg for t=0
    int tidx0 = dir ? (S_-1) : 0;
    const float* xA0 = xg + ((size_t)(tidx0*B_ + b0))*H3_;
    const float* xB0 = xA0 + H3_;
    float xr0 = xA0[j], xz0 = xA0[H_+j], xn0 = xA0[2*H_+j];
    float xr1 = xB0[j], xz1 = xB0[H_+j], xn1 = xB0[2*H_+j];

    int m0r = wid * 16;          // mma warp's row base (wid < 6)

    for (int t = 0; t < S_; t++){
        int tidx = dir ? (S_-1-t) : t;
        int ptidx = dir ? (S_-t) : (t-1);   // previous output time (valid t>=1)

        // stage h from states (prev tidx) split into bf16 hi/lo; t=0 -> zeros
        float hp0, hp1;
        if (t == 0){
            #pragma unroll
            for (int i = 0; i < 8; i++){
                int gi = tid + (i << 8);
                int bb = gi >> 7, kq = gi & 127;
                *(ull*)&hHi[bb*WPAD + kq*4] = 0ULL;
                *(ull*)&hLo[bb*WPAD + kq*4] = 0ULL;
            }
            hp0 = 0.f; hp1 = 0.f;
        } else {
            #pragma unroll
            for (int i = 0; i < 8; i++){
                int gi = tid + (i << 8);
                int bb = gi >> 7, kq = gi & 127;
                const float4* src = (const float4*)(states
                    + ((size_t)((bbase+bb)*S_ + ptidx))*(2*H_) + dir*H_);
                ull hi, lo;
                bsplit4(src[kq], hi, lo);
                *(ull*)&hHi[bb*WPAD + kq*4] = hi;
                *(ull*)&hLo[bb*WPAD + kq*4] = lo;
            }
            hp0 = states[((size_t)b0*S_ + ptidx)*(2*H_) + dir*H_ + j];
            hp1 = states[((size_t)(b0+1)*S_ + ptidx)*(2*H_) + dir*H_ + j];
        }
        // next xg issued early (hidden under mma)
        float nxr0=0,nxz0=0,nxn0=0,nxr1=0,nxz1=0,nxn1=0;
        if (t + 1 < S_){
            int ntidx = dir ? (S_-2-t) : (t+1);
            const float* nA = xg + ((size_t)(ntidx*B_ + b0))*H3_;
            const float* nB = nA + H3_;
            nxr0 = nA[j]; nxz0 = nA[H_+j]; nxn0 = nA[2*H_+j];
            nxr1 = nB[j]; nxz1 = nB[H_+j]; nxn1 = nB[2*H_+j];
        }
        __syncthreads();

        float acc0[4] = {0.f,0.f,0.f,0.f};
        float acc1[4] = {0.f,0.f,0.f,0.f};
        if (wid < 6){
            int rA0 = (m0r + g)*WPAD;
            int rA8 = (m0r + g + 8)*WPAD;
            int rB0 = g*WPAD;
            int rB8 = (8 + g)*WPAD;
            #pragma unroll 4
            for (int kc = 0; kc < 32; kc++){
                int kb = kc*16 + tg*2;
                unsigned ah[4], al[4], b0h[2], b0l[2], b1h[2], b1l[2];
                ah[0] = *(const unsigned*)&wHi[rA0 + kb];
                ah[1] = *(const unsigned*)&wHi[rA8 + kb];
                ah[2] = *(const unsigned*)&wHi[rA0 + kb + 8];
                ah[3] = *(const unsigned*)&wHi[rA8 + kb + 8];
                al[0] = *(const unsigned*)&wLo[rA0 + kb];
                al[1] = *(const unsigned*)&wLo[rA8 + kb];
                al[2] = *(const unsigned*)&wLo[rA0 + kb + 8];
                al[3] = *(const unsigned*)&wLo[rA8 + kb + 8];
                b0h[0] = *(const unsigned*)&hHi[rB0 + kb];
                b0h[1] = *(const unsigned*)&hHi[rB0 + kb + 8];
                b0l[0] = *(const unsigned*)&hLo[rB0 + kb];
                b0l[1] = *(const unsigned*)&hLo[rB0 + kb + 8];
                b1h[0] = *(const unsigned*)&hHi[rB8 + kb];
                b1h[1] = *(const unsigned*)&hHi[rB8 + kb + 8];
                b1l[0] = *(const unsigned*)&hLo[rB8 + kb];
                b1l[1] = *(const unsigned*)&hLo[rB8 + kb + 8];
                mma16816(acc0, ah, b0h);
                mma16816(acc0, ah, b0l);
                mma16816(acc0, al, b0h);
                mma16816(acc1, ah, b1h);
                mma16816(acc1, ah, b1l);
                mma16816(acc1, al, b1h);
            }
        }
        __syncthreads();   // all hHi/hLo reads done -> safe to reuse as epi

        if (wid < 6){
            int r0 = (m0r + g)*16;
            int r8 = (m0r + g + 8)*16;
            epi[r0 + tg*2]          = acc0[0];
            epi[r0 + tg*2 + 1]      = acc0[1];
            epi[r8 + tg*2]          = acc0[2];
            epi[r8 + tg*2 + 1]      = acc0[3];
            epi[r0 + 8 + tg*2]      = acc1[0];
            epi[r0 + 8 + tg*2 + 1]  = acc1[1];
            epi[r8 + 8 + tg*2]      = acc1[2];
            epi[r8 + 8 + tg*2 + 1]  = acc1[3];
        }
        __syncthreads();

        float sr0 = epi[jp*16 + bp*2],        sr1 = epi[jp*16 + bp*2 + 1];
        float sz0 = epi[(32+jp)*16 + bp*2],   sz1 = epi[(32+jp)*16 + bp*2 + 1];
        float sn0 = epi[(64+jp)*16 + bp*2],   sn1 = epi[(64+jp)*16 + bp*2 + 1];

        float r0 = 1.f/(1.f+expf(-(xr0 + sr0 + bhr)));
        float r1 = 1.f/(1.f+expf(-(xr1 + sr1 + bhr)));
        float z0 = 1.f/(1.f+expf(-(xz0 + sz0 + bhz)));
        float z1 = 1.f/(1.f+expf(-(xz1 + sz1 + bhz)));
        float n0 = tanhf(xn0 + r0*(sn0 + bhn));
        float n1 = tanhf(xn1 + r1*(sn1 + bhn));
        float h0 = (1.f-z0)*n0 + z0*hp0;
        float h1 = (1.f-z1)*n1 + z1*hp1;

        states[((size_t)b0*S_ + tidx)*(2*H_) + dir*H_ + j]     = h0;
        states[((size_t)(b0+1)*S_ + tidx)*(2*H_) + dir*H_ + j] = h1;

        if (t + 1 < S_) gbar_grp(grp);

        xr0=nxr0; xz0=nxz0; xn0=nxn0; xr1=nxr1; xz1=nxz1; xn1=nxn1;
    }
}

// ---------------- fused post: alpha softmax + context + final -----------------
// One block per batch. Threads 0..255 compute alpha; all 512 do context+final.
__global__ __launch_bounds__(512) void k_post(const float* __restrict__ states,
                                              const float* __restrict__ att_w2,
                                              const float* __restrict__ lin_w,
                                              const float* __restrict__ lin_b,
                                              float* __restrict__ alpha_out,
                                              float* __restrict__ context_out,
                                              float* __restrict__ out){
    __shared__ float w2s[NH_*A_];
    __shared__ float al[NH_*S_];
    __shared__ float sred[OUT_][17];
    __shared__ float red[OUT_];
    int b = blockIdx.x, tid = threadIdx.x;
    int wid = tid >> 5, lane = tid & 31;
    for (int i = tid; i < NH_*A_; i += 512) w2s[i] = att_w2[i];
    __syncthreads();

    // alpha = m1 @ att_w2^T  (256 threads: s=tid>>2, h=tid&3)
    if (tid < 256){
        int s = tid >> 2, h = tid & 3;
        const float* m1r = g_m1 + ((size_t)(b*S_ + s))*A_;
        float acc = 0.f;
        #pragma unroll 4
        for (int k = 0; k < A_; k++) acc += m1r[k]*w2s[h*A_+k];
        al[h*S_+s] = acc;
    }
    __syncthreads();

    // softmax over S per head (warps 0..3), write alpha_out, keep normalized in al
    if (wid < NH_){
        float v0 = al[wid*S_+lane], v1 = al[wid*S_+lane+32];
        float mx = fmaxf(v0, v1);
        #pragma unroll
        for (int o = 16; o > 0; o >>= 1) mx = fmaxf(mx, __shfl_xor_sync(0xffffffffu, mx, o));
        float e0 = expf(v0-mx), e1 = expf(v1-mx);
        float sm = e0 + e1;
        #pragma unroll
        for (int o = 16; o > 0; o >>= 1) sm += __shfl_xor_sync(0xffffffffu, sm, o);
        float inv = 1.f/sm;
        float a0 = e0*inv, a1 = e1*inv;
        alpha_out[(b*NH_+wid)*S_ + lane]      = a0;
        alpha_out[(b*NH_+wid)*S_ + lane + 32] = a1;
        al[wid*S_+lane]      = a0;
        al[wid*S_+lane + 32] = a1;
    }
    __syncthreads();

    // context: thread tid owns columns (h*2H + tid) and (h*2H + H + tid)
    float a0[NH_], a1[NH_];
    #pragma unroll
    for (int h = 0; h < NH_; h++){ a0[h] = 0.f; a1[h] = 0.f; }
    const float* st = states + (size_t)b*S_*2*H_;
    for (int s = 0; s < S_; s++){
        float v0 = st[s*2*H_ + tid];
        float v1 = st[s*2*H_ + H_ + tid];
        #pragma unroll
        for (int h = 0; h < NH_; h++){
            float a = al[h*S_+s];
            a0[h] += a*v0; a1[h] += a*v1;
        }
    }
    float* cb = context_out + (size_t)b*NH_*2*H_;
    #pragma unroll
    for (int h = 0; h < NH_; h++){
        cb[h*2*H_ + tid]      = a0[h];
        cb[h*2*H_ + H_ + tid] = a1[h];
    }

    // final linear: context (in registers, distributed) @ lin_w^T
    #pragma unroll
    for (int w = 0; w < OUT_; w++){
        const float* lw = lin_w + (size_t)w*4096;
        float p = 0.f;
        #pragma unroll
        for (int h = 0; h < NH_; h++){
            p += a0[h]*lw[h*1024 + tid];
            p += a1[h]*lw[h*1024 + 512 + tid];
        }
        #pragma unroll
        for (int o = 16; o > 0; o >>= 1) p += __shfl_xor_sync(0xffffffffu, p, o);
        if (lane == 0) sred[w][wid] = p;
    }
    __syncthreads();
    if (tid < OUT_){
        float acc = 0.f;
        #pragma unroll
        for (int ww = 0; ww < 16; ww++) acc += sred[tid][ww];
        red[tid] = acc + lin_b[tid];
    }
    __syncthreads();
    if (tid < 32){
        float v = (lane < OUT_) ? red[lane] : -1e30f;
        float mx = v;
        #pragma unroll
        for (int o = 16; o > 0; o >>= 1) mx = fmaxf(mx, __shfl_xor_sync(0xffffffffu, mx, o));
        float e = (lane < OUT_) ? expf(v - mx) : 0.f;
        float sm = e;
        #pragma unroll
        for (int o = 16; o > 0; o >>= 1) sm += __shfl_xor_sync(0xffffffffu, sm, o);
        if (lane < OUT_) out[b*OUT_ + lane] = e/sm;
    }
}

// ---------------- launch ------------------------------------------------------
extern "C" void kernel_launch(void* const* d_in, const int* in_sizes, int n_in,
                              void* d_out, int out_size){
    const float* inputs  = (const float*)d_in[0];
    const float* conv_w  = (const float*)d_in[2];
    const float* conv_b  = (const float*)d_in[3];
    const float* w_embed = (const float*)d_in[4];
    const float* w_ih_f  = (const float*)d_in[5];
    const float* w_hh_f  = (const float*)d_in[6];
    const float* b_ih_f  = (const float*)d_in[7];
    const float* b_hh_f  = (const float*)d_in[8];
    const float* w_ih_b  = (const float*)d_in[9];
    const float* w_hh_b  = (const float*)d_in[10];
    const float* b_ih_b  = (const float*)d_in[11];
    const float* b_hh_b  = (const float*)d_in[12];
    const float* att_w1  = (const float*)d_in[13];
    const float* att_w2  = (const float*)d_in[14];
    const float* lin_w   = (const float*)d_in[15];
    const float* lin_b   = (const float*)d_in[16];

    float* out     = (float*)d_out;
    float* states  = out + STATES_OFF;
    float* context = out + CONTEXT_OFF;
    float* alpha   = out + ALPHA_OFF;

    void *p_vec, *p_emb, *p_xg, *p_m1;
    cudaGetSymbolAddress(&p_vec, g_vec);
    cudaGetSymbolAddress(&p_emb, g_emb);
    cudaGetSymbolAddress(&p_xg,  g_xg);
    cudaGetSymbolAddress(&p_m1,  g_m1);
    float* vec = (float*)p_vec;
    float* emb = (float*)p_emb;
    float* xg0 = (float*)p_xg;
    float* m1  = (float*)p_m1;

    const int conv_smem = P_*D_*4;                       // 65536
    const int gru_smem  = (192*WPAD + 32*WPAD) * 2;      // 231168
    cudaFuncSetAttribute(k_conv_vec, cudaFuncAttributeMaxDynamicSharedMemorySize, conv_smem);
    cudaFuncSetAttribute(k_gru,      cudaFuncAttributeMaxDynamicSharedMemorySize, gru_smem);

    // 1) conv + weighted-sum (inputs read once)
    k_conv_vec<<<BS_, 256, conv_smem>>>(inputs, conv_w, conv_b);
    // 2) emb = clip(vec @ w_embed^T)  [split-bf16 HMMA + ldmatrix]
    k_bgemm<<<dim3(E_/64, BS_/128, 1), 256>>>(vec, w_embed, w_embed, emb,
                                              BS_, E_, D_, nullptr, nullptr, 1, 0);
    // 3) xg = emb([S,B] permuted) @ w_ih^T + b_ih, BOTH dirs via grid.z
    k_bgemm<<<dim3(H3_/64, BS_/128, 2), 256>>>(emb, w_ih_f, w_ih_b, xg0,
                                               BS_, H3_, E_, b_ih_f, b_ih_b, 0, 1);
    // 4) persistent bidirectional GRU (HMMA recurrence, fence-free) -> states
    k_gru<<<128, 256, gru_smem>>>(w_hh_f, w_hh_b, b_hh_f, b_hh_b, states);
    // 5) m1 = clip(states @ att_w1^T)  [split-bf16 HMMA + ldmatrix]
    k_bgemm<<<dim3(A_/64, BS_/128, 1), 256>>>(states, att_w1, att_w1, m1,
                                              BS_, A_, 2*H_, nullptr, nullptr, 1, 0);
    // 6-8) fused alpha softmax + context + final linear/softmax
    k_post<<<B_, 512>>>(states, att_w2, lin_w, lin_b, alpha, context, out);
}